// round 3
// baseline (speedup 1.0000x reference)
#include <cuda_runtime.h>
#include <math.h>

// Problem constants
#define BB 2
#define LL 4096
#define DD 512
#define HH 8
#define EE 64
#define BH 16          // B*H
#define CC 64          // chunk length
#define NC 64          // chunks per (b,h) = L/CC
#define MR 8192        // B*L rows

// ---------------- scratch (device globals; no allocation allowed) ------------
__device__ float g_qf[BB*HH*LL*EE];     // q features (later q_decayed), (B,H,L,E)
__device__ float g_kf[BB*HH*LL*EE];     // k features (later k_decayed)
__device__ float g_v [BB*HH*LL*EE];     // v, (B,H,L,E)
__device__ float g_ll[BB*HH*LL];        // log-lambda, then clipped cumsum (B,H,L)
__device__ float g_chunkA[BH*NC*EE*EE]; // per-chunk K^T V, then exclusive prefix (state in)
__device__ float g_chunkZ[BH*NC*EE];    // per-chunk colsum(K), then exclusive prefix
__device__ float g_att[MR*DD];          // attention output (B,L,D)

// ---------------- K1: QKV GEMM + feature map epilogue ------------------------
// C[m][n] = sum_k x[m][k]*qkv_w[n][k] + qkv_b[n];  M=8192, N=1536, K=512
__global__ void qkv_gemm_kernel(const float* __restrict__ x,
                                const float* __restrict__ w,
                                const float* __restrict__ bias) {
    __shared__ float As[16][64];
    __shared__ float Ws[16][64];
    const int nb = blockIdx.x, mb = blockIdx.y;
    const int t = threadIdx.x;
    const int ty = t >> 4, tx = t & 15;
    const int lr = t >> 2;          // 0..63 load row
    const int lc = (t & 3) << 2;    // 0,4,8,12 load k-offset
    float acc[4][4] = {};
    const float* Ap = x + (size_t)(mb*64 + lr)*512 + lc;
    const float* Wp = w + (size_t)(nb*64 + lr)*512 + lc;
    for (int kt = 0; kt < 512; kt += 16) {
        float4 a = *(const float4*)(Ap + kt);
        float4 b = *(const float4*)(Wp + kt);
        As[lc+0][lr]=a.x; As[lc+1][lr]=a.y; As[lc+2][lr]=a.z; As[lc+3][lr]=a.w;
        Ws[lc+0][lr]=b.x; Ws[lc+1][lr]=b.y; Ws[lc+2][lr]=b.z; Ws[lc+3][lr]=b.w;
        __syncthreads();
        #pragma unroll
        for (int kk = 0; kk < 16; kk++) {
            float4 av = *(const float4*)&As[kk][ty*4];
            float4 bv = *(const float4*)&Ws[kk][tx*4];
            acc[0][0]+=av.x*bv.x; acc[0][1]+=av.x*bv.y; acc[0][2]+=av.x*bv.z; acc[0][3]+=av.x*bv.w;
            acc[1][0]+=av.y*bv.x; acc[1][1]+=av.y*bv.y; acc[1][2]+=av.y*bv.z; acc[1][3]+=av.y*bv.w;
            acc[2][0]+=av.z*bv.x; acc[2][1]+=av.z*bv.y; acc[2][2]+=av.z*bv.z; acc[2][3]+=av.z*bv.w;
            acc[3][0]+=av.w*bv.x; acc[3][1]+=av.w*bv.y; acc[3][2]+=av.w*bv.z; acc[3][3]+=av.w*bv.w;
        }
        __syncthreads();
    }
    // epilogue: feature map + scatter to (B,H,L,E)
    #pragma unroll
    for (int i = 0; i < 4; i++) {
        int m = mb*64 + ty*4 + i;
        int b = m >> 12, l = m & 4095;
        #pragma unroll
        for (int j = 0; j < 4; j++) {
            int n = nb*64 + tx*4 + j;
            float val = acc[i][j] + bias[n];
            int part = n >> 9;          // 0=q,1=k,2=v
            int hh = (n >> 6) & 7;
            int e = n & 63;
            size_t dst = ((size_t)(b*8 + hh)*4096 + l)*64 + e;
            if (part == 0) {
                float f = (val > 0.f) ? (val + 1.f) : expf(val);   // elu+1
                g_qf[dst] = f * 0.125f;                             // / sqrt(64)
            } else if (part == 1) {
                g_kf[dst] = (val > 0.f) ? (val + 1.f) : expf(val);
            } else {
                g_v[dst] = val;
            }
        }
    }
}

// ---------------- K1b: decay logits -> log lambda ----------------------------
__global__ void decay_kernel(const float* __restrict__ x,
                             const float* __restrict__ dw,
                             const float* __restrict__ db) {
    int warp = threadIdx.x >> 5, lane = threadIdx.x & 31;
    int m = blockIdx.x*8 + warp;           // row 0..8191
    const float* xr = x + (size_t)m*512;
    float xv[16];
    #pragma unroll
    for (int i = 0; i < 16; i++) xv[i] = xr[lane + 32*i];
    int b = m >> 12, l = m & 4095;
    #pragma unroll
    for (int h = 0; h < 8; h++) {
        const float* wr = dw + h*512;
        float s = 0.f;
        #pragma unroll
        for (int i = 0; i < 16; i++) s += xv[i]*wr[lane + 32*i];
        #pragma unroll
        for (int o = 16; o > 0; o >>= 1) s += __shfl_xor_sync(0xffffffffu, s, o);
        if (lane == 0) {
            float z = s + db[h];
            float lam = 0.9f + 0.1f/(1.f + expf(-z));
            g_ll[(size_t)(b*8 + h)*4096 + l] = logf(fmaxf(lam, 1e-6f));
        }
    }
}

// ---------------- K2: per-(b,h) cumsum of log lambda, clipped ----------------
__global__ void cumsum_kernel() {
    int bh = blockIdx.x;
    float* p = g_ll + (size_t)bh*4096;
    int t = threadIdx.x;   // 128 threads, 32 elems each
    __shared__ float sums[128];
    __shared__ float offs[128];
    int base = t*32;
    float s = 0.f;
    for (int i = 0; i < 32; i++) s += p[base+i];
    sums[t] = s;
    __syncthreads();
    if (t == 0) { float r = 0.f; for (int i = 0; i < 128; i++) { offs[i] = r; r += sums[i]; } }
    __syncthreads();
    float run = offs[t];
    for (int i = 0; i < 32; i++) {
        run += p[base+i];
        p[base+i] = fminf(fmaxf(run, -50.f), 50.f);
    }
}

// ---------------- K2b: qd = qf*exp(cum), kd = kf*exp(-cum) -------------------
__global__ void apply_decay_kernel() {
    int v = blockIdx.x*256 + threadIdx.x;     // float4 index; total 1048576
    int bhl = v >> 4;                          // 16 float4 per (b,h,l)
    float a = g_ll[bhl];
    float eq = expf(a), ek = expf(-a);
    float4 q = reinterpret_cast<float4*>(g_qf)[v];
    float4 k = reinterpret_cast<float4*>(g_kf)[v];
    q.x*=eq; q.y*=eq; q.z*=eq; q.w*=eq;
    k.x*=ek; k.y*=ek; k.z*=ek; k.w*=ek;
    reinterpret_cast<float4*>(g_qf)[v] = q;
    reinterpret_cast<float4*>(g_kf)[v] = k;
}

// ---------------- K3a: per-chunk A = K^T V (64x64), z = colsum(K) ------------
__global__ void chunk_sum_kernel() {
    __shared__ float Ks[64][68];
    __shared__ float Vs[64][68];
    int c = blockIdx.x, bh = blockIdx.y;
    int t = threadIdx.x;
    int ty = t >> 4, tx = t & 15;
    size_t base = ((size_t)bh*64 + c)*4096;   // chunk of 64 tokens * 64 feats
    #pragma unroll
    for (int r = 0; r < 4; r++) {
        int vi = t + 256*r;                   // 1024 float4s
        int s = vi >> 4, e0 = (vi & 15) << 2;
        float4 kv = *(const float4*)(g_kf + base + s*64 + e0);
        float4 vv = *(const float4*)(g_v  + base + s*64 + e0);
        *(float4*)&Ks[s][e0] = kv;
        *(float4*)&Vs[s][e0] = vv;
    }
    __syncthreads();
    float acc[4][4] = {};
    #pragma unroll 8
    for (int s = 0; s < 64; s++) {
        float4 av = *(const float4*)&Ks[s][ty*4];
        float4 bv = *(const float4*)&Vs[s][tx*4];
        acc[0][0]+=av.x*bv.x; acc[0][1]+=av.x*bv.y; acc[0][2]+=av.x*bv.z; acc[0][3]+=av.x*bv.w;
        acc[1][0]+=av.y*bv.x; acc[1][1]+=av.y*bv.y; acc[1][2]+=av.y*bv.z; acc[1][3]+=av.y*bv.w;
        acc[2][0]+=av.z*bv.x; acc[2][1]+=av.z*bv.y; acc[2][2]+=av.z*bv.z; acc[2][3]+=av.z*bv.w;
        acc[3][0]+=av.w*bv.x; acc[3][1]+=av.w*bv.y; acc[3][2]+=av.w*bv.z; acc[3][3]+=av.w*bv.w;
    }
    size_t abase = ((size_t)bh*64 + c)*4096;
    #pragma unroll
    for (int i = 0; i < 4; i++) {
        float4 o = make_float4(acc[i][0], acc[i][1], acc[i][2], acc[i][3]);
        *(float4*)(g_chunkA + abase + (ty*4 + i)*64 + tx*4) = o;
    }
    if (t < 64) {
        float zs = 0.f;
        for (int s = 0; s < 64; s++) zs += Ks[s][t];
        g_chunkZ[((size_t)bh*64 + c)*64 + t] = zs;
    }
}

// ---------------- K3b: in-place exclusive prefix over chunks -----------------
__global__ void chunk_scan_kernel() {
    int bh = blockIdx.x;
    int t = threadIdx.x;   // 256
    float run[16];
    #pragma unroll
    for (int j = 0; j < 16; j++) run[j] = 0.f;
    size_t base = (size_t)bh*64*4096;
    for (int c = 0; c < 64; c++) {
        float* p = g_chunkA + base + (size_t)c*4096;
        #pragma unroll
        for (int j = 0; j < 16; j++) {
            int idx = t + 256*j;
            float tmp = p[idx];
            p[idx] = run[j];
            run[j] += tmp;
        }
    }
    if (t < 64) {
        float rz = 0.f;
        float* z = g_chunkZ + (size_t)bh*64*64;
        for (int c = 0; c < 64; c++) { float tmp = z[c*64 + t]; z[c*64 + t] = rz; rz += tmp; }
    }
}

// ---------------- K3c: chunk output ------------------------------------------
// O = tril(Q K^T) V + Q @ S_in ; den = rowsum(tril(P)) + Q.z_in ; att = O/den
__global__ void chunk_out_kernel() {
    extern __shared__ float sm[];
    float* QdT = sm;               // [64][68], QdT[e][t]
    float* KV  = QdT + 64*68;      // stage1: KdT[e][s]; stage2: V[s][f]
    float* PT  = KV  + 64*68;      // PT[s][t]
    float* Inb = PT  + 64*68;      // In[e][f]
    float* zin = Inb + 64*68;      // [64]
    float* den = zin + 64;         // [64]

    int c = blockIdx.x, bh = blockIdx.y;
    int t = threadIdx.x;
    int ty = t >> 4, tx = t & 15;
    if (t < 64) den[t] = 0.f;

    size_t base = ((size_t)bh*64 + c)*4096;
    // load Q, K transposed [e][token]
    #pragma unroll
    for (int r = 0; r < 4; r++) {
        int vi = t + 256*r;
        int s = vi >> 4, e0 = (vi & 15) << 2;
        float4 q = *(const float4*)(g_qf + base + s*64 + e0);
        float4 k = *(const float4*)(g_kf + base + s*64 + e0);
        QdT[(e0+0)*68 + s] = q.x; QdT[(e0+1)*68 + s] = q.y;
        QdT[(e0+2)*68 + s] = q.z; QdT[(e0+3)*68 + s] = q.w;
        KV [(e0+0)*68 + s] = k.x; KV [(e0+1)*68 + s] = k.y;
        KV [(e0+2)*68 + s] = k.z; KV [(e0+3)*68 + s] = k.w;
    }
    __syncthreads();

    // stage1: P[t][s] = sum_e Q[t][e]K[s][e], causal mask, store PT, den rowsums
    {
        float acc[4][4] = {};
        #pragma unroll 8
        for (int e = 0; e < 64; e++) {
            float4 av = *(const float4*)&QdT[e*68 + ty*4];
            float4 bv = *(const float4*)&KV [e*68 + tx*4];
            acc[0][0]+=av.x*bv.x; acc[0][1]+=av.x*bv.y; acc[0][2]+=av.x*bv.z; acc[0][3]+=av.x*bv.w;
            acc[1][0]+=av.y*bv.x; acc[1][1]+=av.y*bv.y; acc[1][2]+=av.y*bv.z; acc[1][3]+=av.y*bv.w;
            acc[2][0]+=av.z*bv.x; acc[2][1]+=av.z*bv.y; acc[2][2]+=av.z*bv.z; acc[2][3]+=av.z*bv.w;
            acc[3][0]+=av.w*bv.x; acc[3][1]+=av.w*bv.y; acc[3][2]+=av.w*bv.z; acc[3][3]+=av.w*bv.w;
        }
        #pragma unroll
        for (int i = 0; i < 4; i++) {
            int tg = ty*4 + i;
            float rs = 0.f;
            #pragma unroll
            for (int j = 0; j < 4; j++) {
                int sg = tx*4 + j;
                float v = (sg <= tg) ? acc[i][j] : 0.f;
                PT[sg*68 + tg] = v;
                rs += v;
            }
            atomicAdd(&den[tg], rs);
        }
    }
    __syncthreads();

    // load V and In (natural layouts), z_in
    #pragma unroll
    for (int r = 0; r < 4; r++) {
        int vi = t + 256*r;
        int s = vi >> 4, e0 = (vi & 15) << 2;
        *(float4*)&KV [s*68 + e0] = *(const float4*)(g_v + base + s*64 + e0);
        *(float4*)&Inb[s*68 + e0] = *(const float4*)(g_chunkA + base + s*64 + e0);
    }
    if (t < 64) zin[t] = g_chunkZ[((size_t)bh*64 + c)*64 + t];
    __syncthreads();

    if (t < 64) {
        float s = 0.f;
        for (int e = 0; e < 64; e++) s += QdT[e*68 + t]*zin[e];
        den[t] += s;
    }
    __syncthreads();

    // stage2: O = PT^T @ V + QdT^T @ In
    float acc[4][4] = {};
    #pragma unroll 8
    for (int s = 0; s < 64; s++) {
        float4 wv = *(const float4*)&PT[s*68 + ty*4];
        float4 xv = *(const float4*)&KV[s*68 + tx*4];
        acc[0][0]+=wv.x*xv.x; acc[0][1]+=wv.x*xv.y; acc[0][2]+=wv.x*xv.z; acc[0][3]+=wv.x*xv.w;
        acc[1][0]+=wv.y*xv.x; acc[1][1]+=wv.y*xv.y; acc[1][2]+=wv.y*xv.z; acc[1][3]+=wv.y*xv.w;
        acc[2][0]+=wv.z*xv.x; acc[2][1]+=wv.z*xv.y; acc[2][2]+=wv.z*xv.z; acc[2][3]+=wv.z*xv.w;
        acc[3][0]+=wv.w*xv.x; acc[3][1]+=wv.w*xv.y; acc[3][2]+=wv.w*xv.z; acc[3][3]+=wv.w*xv.w;
    }
    #pragma unroll 8
    for (int e = 0; e < 64; e++) {
        float4 wv = *(const float4*)&QdT[e*68 + ty*4];
        float4 xv = *(const float4*)&Inb[e*68 + tx*4];
        acc[0][0]+=wv.x*xv.x; acc[0][1]+=wv.x*xv.y; acc[0][2]+=wv.x*xv.z; acc[0][3]+=wv.x*xv.w;
        acc[1][0]+=wv.y*xv.x; acc[1][1]+=wv.y*xv.y; acc[1][2]+=wv.y*xv.z; acc[1][3]+=wv.y*xv.w;
        acc[2][0]+=wv.z*xv.x; acc[2][1]+=wv.z*xv.y; acc[2][2]+=wv.z*xv.z; acc[2][3]+=wv.z*xv.w;
        acc[3][0]+=wv.w*xv.x; acc[3][1]+=wv.w*xv.y; acc[3][2]+=wv.w*xv.z; acc[3][3]+=wv.w*xv.w;
    }
    int b = bh >> 3, h = bh & 7;
    #pragma unroll
    for (int i = 0; i < 4; i++) {
        int tg = ty*4 + i;
        float inv = 1.f/(den[tg] + 1e-6f);
        int l = c*64 + tg;
        float4 o = make_float4(acc[i][0]*inv, acc[i][1]*inv, acc[i][2]*inv, acc[i][3]*inv);
        *(float4*)(g_att + ((size_t)b*4096 + l)*512 + h*64 + tx*4) = o;
    }
}

// ---------------- K4: out projection GEMM ------------------------------------
__global__ void out_gemm_kernel(const float* __restrict__ w,
                                const float* __restrict__ bias,
                                float* __restrict__ out) {
    __shared__ float As[16][64];
    __shared__ float Ws[16][64];
    const int nb = blockIdx.x, mb = blockIdx.y;
    const int t = threadIdx.x;
    const int ty = t >> 4, tx = t & 15;
    const int lr = t >> 2;
    const int lc = (t & 3) << 2;
    float acc[4][4] = {};
    const float* Ap = g_att + (size_t)(mb*64 + lr)*512 + lc;
    const float* Wp = w + (size_t)(nb*64 + lr)*512 + lc;
    for (int kt = 0; kt < 512; kt += 16) {
        float4 a = *(const float4*)(Ap + kt);
        float4 b = *(const float4*)(Wp + kt);
        As[lc+0][lr]=a.x; As[lc+1][lr]=a.y; As[lc+2][lr]=a.z; As[lc+3][lr]=a.w;
        Ws[lc+0][lr]=b.x; Ws[lc+1][lr]=b.y; Ws[lc+2][lr]=b.z; Ws[lc+3][lr]=b.w;
        __syncthreads();
        #pragma unroll
        for (int kk = 0; kk < 16; kk++) {
            float4 av = *(const float4*)&As[kk][ty*4];
            float4 bv = *(const float4*)&Ws[kk][tx*4];
            acc[0][0]+=av.x*bv.x; acc[0][1]+=av.x*bv.y; acc[0][2]+=av.x*bv.z; acc[0][3]+=av.x*bv.w;
            acc[1][0]+=av.y*bv.x; acc[1][1]+=av.y*bv.y; acc[1][2]+=av.y*bv.z; acc[1][3]+=av.y*bv.w;
            acc[2][0]+=av.z*bv.x; acc[2][1]+=av.z*bv.y; acc[2][2]+=av.z*bv.z; acc[2][3]+=av.z*bv.w;
            acc[3][0]+=av.w*bv.x; acc[3][1]+=av.w*bv.y; acc[3][2]+=av.w*bv.z; acc[3][3]+=av.w*bv.w;
        }
        __syncthreads();
    }
    #pragma unroll
    for (int i = 0; i < 4; i++) {
        int m = mb*64 + ty*4 + i;
        #pragma unroll
        for (int j = 0; j < 4; j++) {
            int n = nb*64 + tx*4 + j;
            out[(size_t)m*512 + n] = acc[i][j] + bias[n];
        }
    }
}

// ---------------- K5: in-place RMSNorm ---------------------------------------
__global__ void rmsnorm_kernel(float* __restrict__ out,
                               const float* __restrict__ scale) {
    int m = blockIdx.x;
    int t = threadIdx.x;    // 128 threads, 4 floats each
    float4 v = *(float4*)(out + (size_t)m*512 + t*4);
    float ss = v.x*v.x + v.y*v.y + v.z*v.z + v.w*v.w;
    #pragma unroll
    for (int o = 16; o > 0; o >>= 1) ss += __shfl_xor_sync(0xffffffffu, ss, o);
    __shared__ float red[4];
    if ((t & 31) == 0) red[t >> 5] = ss;
    __syncthreads();
    float tot = red[0] + red[1] + red[2] + red[3];
    float inv = rsqrtf(tot * (1.f/512.f) + 1e-8f);
    float4 sc = *(const float4*)(scale + t*4);
    v.x *= inv*sc.x; v.y *= inv*sc.y; v.z *= inv*sc.z; v.w *= inv*sc.w;
    *(float4*)(out + (size_t)m*512 + t*4) = v;
}

// ---------------- launch ------------------------------------------------------
extern "C" void kernel_launch(void* const* d_in, const int* in_sizes, int n_in,
                              void* d_out, int out_size) {
    const float* x          = (const float*)d_in[0];
    const float* qkv_w      = (const float*)d_in[1];
    const float* qkv_b      = (const float*)d_in[2];
    const float* out_w      = (const float*)d_in[3];
    const float* out_b      = (const float*)d_in[4];
    const float* decay_w    = (const float*)d_in[5];
    const float* decay_b    = (const float*)d_in[6];
    const float* norm_scale = (const float*)d_in[7];
    float* out = (float*)d_out;

    qkv_gemm_kernel<<<dim3(24, 128), 256>>>(x, qkv_w, qkv_b);
    decay_kernel<<<1024, 256>>>(x, decay_w, decay_b);
    cumsum_kernel<<<16, 128>>>();
    apply_decay_kernel<<<4096, 256>>>();
    chunk_sum_kernel<<<dim3(64, 16), 256>>>();
    chunk_scan_kernel<<<16, 256>>>();

    const int dyn = (4*64*68 + 128) * sizeof(float);   // 70144 B
    cudaFuncSetAttribute(chunk_out_kernel,
                         cudaFuncAttributeMaxDynamicSharedMemorySize, dyn);
    chunk_out_kernel<<<dim3(64, 16), 256, dyn>>>();

    out_gemm_kernel<<<dim3(8, 128), 256>>>(out_w, out_b, out);
    rmsnorm_kernel<<<8192, 128>>>(out, norm_scale);
}

// round 5
// speedup vs baseline: 2.1557x; 2.1557x over previous
#include <cuda_runtime.h>
#include <math.h>

// Problem constants
#define BB 2
#define LL 4096
#define DD 512
#define HH 8
#define EE 64
#define BH 16
#define CC 64
#define NC 64
#define MR 8192

// ---------------- scratch ----------------
__device__ float g_qf[BB*HH*LL*EE];
__device__ float g_kf[BB*HH*LL*EE];
__device__ float g_v [BB*HH*LL*EE];
__device__ float g_ll[BB*HH*LL];
__device__ float g_chunkA[BH*NC*EE*EE];
__device__ float g_chunkZ[BH*NC*EE];
__device__ float g_att[MR*DD];

// ---------------- tf32 helpers ----------------
__device__ __forceinline__ unsigned f2tf32(float f) {
    unsigned u;
    asm("cvt.rna.tf32.f32 %0, %1;" : "=r"(u) : "f"(f));
    return u;
}

#define MMA_TF32(c0,c1,c2,c3,a0,a1,a2,a3,b0,b1)                           \
    asm volatile("mma.sync.aligned.m16n8k8.row.col.f32.tf32.tf32.f32 "    \
        "{%0,%1,%2,%3}, {%4,%5,%6,%7}, {%8,%9}, {%0,%1,%2,%3};"           \
        : "+f"(c0), "+f"(c1), "+f"(c2), "+f"(c3)                          \
        : "r"(a0), "r"(a1), "r"(a2), "r"(a3), "r"(b0), "r"(b1))

// Shared tile stride (floats): 36 -> conflict-free frag loads, 16B-aligned rows
#define TS 36

// ================= K1: QKV GEMM (tf32 MMA) + feature-map scatter =============
// C[m][n] = sum_k x[m][k]*w[n][k] + b[n];  M=8192, N=1536, K=512
__global__ __launch_bounds__(256)
void qkv_gemm_kernel(const float* __restrict__ x,
                     const float* __restrict__ w,
                     const float* __restrict__ bias) {
    __shared__ unsigned As[128*TS];
    __shared__ unsigned Bs[128*TS];
    const int nb = blockIdx.x, mb = blockIdx.y;
    const int t = threadIdx.x;
    const int wid = t >> 5, lane = t & 31;
    const int wrow = wid >> 2, wcol = wid & 3;     // 2 x 4 warps
    const int lr4 = lane >> 2, lc4 = lane & 3;

    float acc[4][4][4];
    #pragma unroll
    for (int i = 0; i < 4; i++)
        #pragma unroll
        for (int j = 0; j < 4; j++)
            #pragma unroll
            for (int c = 0; c < 4; c++) acc[i][j][c] = 0.f;

    const float* Abase = x + (size_t)(mb*128)*512;
    const float* Bbase = w + (size_t)(nb*128)*512;

    for (int kt = 0; kt < 512; kt += 32) {
        // load 128x32 A and B tiles (1024 float4 each, 4 per thread)
        #pragma unroll
        for (int r = 0; r < 4; r++) {
            int vi = t + 256*r;
            int row = vi >> 3, k4 = (vi & 7) << 2;
            float4 a = *(const float4*)(Abase + (size_t)row*512 + kt + k4);
            float4 b = *(const float4*)(Bbase + (size_t)row*512 + kt + k4);
            unsigned* pa = &As[row*TS + k4];
            unsigned* pb = &Bs[row*TS + k4];
            pa[0]=f2tf32(a.x); pa[1]=f2tf32(a.y); pa[2]=f2tf32(a.z); pa[3]=f2tf32(a.w);
            pb[0]=f2tf32(b.x); pb[1]=f2tf32(b.y); pb[2]=f2tf32(b.z); pb[3]=f2tf32(b.w);
        }
        __syncthreads();
        #pragma unroll
        for (int ks = 0; ks < 4; ks++) {
            const int k0 = ks*8;
            unsigned af[4][4], bf[4][2];
            #pragma unroll
            for (int mt = 0; mt < 4; mt++) {
                int mbase = wrow*64 + mt*16;
                af[mt][0] = As[(mbase + lr4    )*TS + k0 + lc4    ];
                af[mt][1] = As[(mbase + lr4 + 8)*TS + k0 + lc4    ];
                af[mt][2] = As[(mbase + lr4    )*TS + k0 + lc4 + 4];
                af[mt][3] = As[(mbase + lr4 + 8)*TS + k0 + lc4 + 4];
            }
            #pragma unroll
            for (int nt = 0; nt < 4; nt++) {
                int nbase = wcol*32 + nt*8;
                bf[nt][0] = Bs[(nbase + lr4)*TS + k0 + lc4    ];
                bf[nt][1] = Bs[(nbase + lr4)*TS + k0 + lc4 + 4];
            }
            #pragma unroll
            for (int mt = 0; mt < 4; mt++)
                #pragma unroll
                for (int nt = 0; nt < 4; nt++)
                    MMA_TF32(acc[mt][nt][0], acc[mt][nt][1], acc[mt][nt][2], acc[mt][nt][3],
                             af[mt][0], af[mt][1], af[mt][2], af[mt][3],
                             bf[nt][0], bf[nt][1]);
        }
        __syncthreads();
    }

    // epilogue: bias + feature map + scatter to (B,H,L,E)
    #pragma unroll
    for (int mt = 0; mt < 4; mt++) {
        #pragma unroll
        for (int nt = 0; nt < 4; nt++) {
            #pragma unroll
            for (int ci = 0; ci < 4; ci++) {
                int m = mb*128 + wrow*64 + mt*16 + lr4 + 8*(ci >> 1);
                int n = nb*128 + wcol*32 + nt*8 + lc4*2 + (ci & 1);
                float val = acc[mt][nt][ci] + bias[n];
                int b = m >> 12, l = m & 4095;
                int part = n >> 9, hh = (n >> 6) & 7, e = n & 63;
                size_t dst = ((size_t)(b*8 + hh)*4096 + l)*64 + e;
                if (part == 0) {
                    float f = (val > 0.f) ? (val + 1.f) : expf(val);
                    g_qf[dst] = f * 0.125f;
                } else if (part == 1) {
                    g_kf[dst] = (val > 0.f) ? (val + 1.f) : expf(val);
                } else {
                    g_v[dst] = val;
                }
            }
        }
    }
}

// ================= K4: out projection GEMM (tf32 MMA) ========================
__global__ __launch_bounds__(256)
void out_gemm_kernel(const float* __restrict__ w,
                     const float* __restrict__ bias,
                     float* __restrict__ out) {
    __shared__ unsigned As[128*TS];
    __shared__ unsigned Bs[128*TS];
    const int nb = blockIdx.x, mb = blockIdx.y;
    const int t = threadIdx.x;
    const int wid = t >> 5, lane = t & 31;
    const int wrow = wid >> 2, wcol = wid & 3;
    const int lr4 = lane >> 2, lc4 = lane & 3;

    float acc[4][4][4];
    #pragma unroll
    for (int i = 0; i < 4; i++)
        #pragma unroll
        for (int j = 0; j < 4; j++)
            #pragma unroll
            for (int c = 0; c < 4; c++) acc[i][j][c] = 0.f;

    const float* Abase = g_att + (size_t)(mb*128)*512;
    const float* Bbase = w + (size_t)(nb*128)*512;

    for (int kt = 0; kt < 512; kt += 32) {
        #pragma unroll
        for (int r = 0; r < 4; r++) {
            int vi = t + 256*r;
            int row = vi >> 3, k4 = (vi & 7) << 2;
            float4 a = *(const float4*)(Abase + (size_t)row*512 + kt + k4);
            float4 b = *(const float4*)(Bbase + (size_t)row*512 + kt + k4);
            unsigned* pa = &As[row*TS + k4];
            unsigned* pb = &Bs[row*TS + k4];
            pa[0]=f2tf32(a.x); pa[1]=f2tf32(a.y); pa[2]=f2tf32(a.z); pa[3]=f2tf32(a.w);
            pb[0]=f2tf32(b.x); pb[1]=f2tf32(b.y); pb[2]=f2tf32(b.z); pb[3]=f2tf32(b.w);
        }
        __syncthreads();
        #pragma unroll
        for (int ks = 0; ks < 4; ks++) {
            const int k0 = ks*8;
            unsigned af[4][4], bf[4][2];
            #pragma unroll
            for (int mt = 0; mt < 4; mt++) {
                int mbase = wrow*64 + mt*16;
                af[mt][0] = As[(mbase + lr4    )*TS + k0 + lc4    ];
                af[mt][1] = As[(mbase + lr4 + 8)*TS + k0 + lc4    ];
                af[mt][2] = As[(mbase + lr4    )*TS + k0 + lc4 + 4];
                af[mt][3] = As[(mbase + lr4 + 8)*TS + k0 + lc4 + 4];
            }
            #pragma unroll
            for (int nt = 0; nt < 4; nt++) {
                int nbase = wcol*32 + nt*8;
                bf[nt][0] = Bs[(nbase + lr4)*TS + k0 + lc4    ];
                bf[nt][1] = Bs[(nbase + lr4)*TS + k0 + lc4 + 4];
            }
            #pragma unroll
            for (int mt = 0; mt < 4; mt++)
                #pragma unroll
                for (int nt = 0; nt < 4; nt++)
                    MMA_TF32(acc[mt][nt][0], acc[mt][nt][1], acc[mt][nt][2], acc[mt][nt][3],
                             af[mt][0], af[mt][1], af[mt][2], af[mt][3],
                             bf[nt][0], bf[nt][1]);
        }
        __syncthreads();
    }

    #pragma unroll
    for (int mt = 0; mt < 4; mt++) {
        #pragma unroll
        for (int nt = 0; nt < 4; nt++) {
            #pragma unroll
            for (int ci = 0; ci < 4; ci++) {
                int m = mb*128 + wrow*64 + mt*16 + lr4 + 8*(ci >> 1);
                int n = nb*128 + wcol*32 + nt*8 + lc4*2 + (ci & 1);
                out[(size_t)m*512 + n] = acc[mt][nt][ci] + bias[n];
            }
        }
    }
}

// ---------------- K1b: decay logits -> log lambda ----------------------------
__global__ void decay_kernel(const float* __restrict__ x,
                             const float* __restrict__ dw,
                             const float* __restrict__ db) {
    int warp = threadIdx.x >> 5, lane = threadIdx.x & 31;
    int m = blockIdx.x*8 + warp;
    const float* xr = x + (size_t)m*512;
    float xv[16];
    #pragma unroll
    for (int i = 0; i < 16; i++) xv[i] = xr[lane + 32*i];
    int b = m >> 12, l = m & 4095;
    #pragma unroll
    for (int h = 0; h < 8; h++) {
        const float* wr = dw + h*512;
        float s = 0.f;
        #pragma unroll
        for (int i = 0; i < 16; i++) s += xv[i]*wr[lane + 32*i];
        #pragma unroll
        for (int o = 16; o > 0; o >>= 1) s += __shfl_xor_sync(0xffffffffu, s, o);
        if (lane == 0) {
            float z = s + db[h];
            float lam = 0.9f + 0.1f/(1.f + expf(-z));
            g_ll[(size_t)(b*8 + h)*4096 + l] = logf(fmaxf(lam, 1e-6f));
        }
    }
}

// ---------------- K2: per-(b,h) cumsum of log lambda, clipped ----------------
__global__ void cumsum_kernel() {
    int bh = blockIdx.x;
    float* p = g_ll + (size_t)bh*4096;
    int t = threadIdx.x;
    __shared__ float sums[128];
    __shared__ float offs[128];
    int base = t*32;
    float s = 0.f;
    for (int i = 0; i < 32; i++) s += p[base+i];
    sums[t] = s;
    __syncthreads();
    if (t == 0) { float r = 0.f; for (int i = 0; i < 128; i++) { offs[i] = r; r += sums[i]; } }
    __syncthreads();
    float run = offs[t];
    for (int i = 0; i < 32; i++) {
        run += p[base+i];
        p[base+i] = fminf(fmaxf(run, -50.f), 50.f);
    }
}

// ---------------- K2b: qd = qf*exp(cum), kd = kf*exp(-cum) -------------------
__global__ void apply_decay_kernel() {
    int v = blockIdx.x*256 + threadIdx.x;
    int bhl = v >> 4;
    float a = g_ll[bhl];
    float eq = expf(a), ek = expf(-a);
    float4 q = reinterpret_cast<float4*>(g_qf)[v];
    float4 k = reinterpret_cast<float4*>(g_kf)[v];
    q.x*=eq; q.y*=eq; q.z*=eq; q.w*=eq;
    k.x*=ek; k.y*=ek; k.z*=ek; k.w*=ek;
    reinterpret_cast<float4*>(g_qf)[v] = q;
    reinterpret_cast<float4*>(g_kf)[v] = k;
}

// ---------------- K3a: per-chunk A = K^T V, z = colsum(K) --------------------
__global__ void chunk_sum_kernel() {
    __shared__ float Ks[64][68];
    __shared__ float Vs[64][68];
    int c = blockIdx.x, bh = blockIdx.y;
    int t = threadIdx.x;
    int ty = t >> 4, tx = t & 15;
    size_t base = ((size_t)bh*64 + c)*4096;
    #pragma unroll
    for (int r = 0; r < 4; r++) {
        int vi = t + 256*r;
        int s = vi >> 4, e0 = (vi & 15) << 2;
        float4 kv = *(const float4*)(g_kf + base + s*64 + e0);
        float4 vv = *(const float4*)(g_v  + base + s*64 + e0);
        *(float4*)&Ks[s][e0] = kv;
        *(float4*)&Vs[s][e0] = vv;
    }
    __syncthreads();
    float acc[4][4] = {};
    #pragma unroll 8
    for (int s = 0; s < 64; s++) {
        float4 av = *(const float4*)&Ks[s][ty*4];
        float4 bv = *(const float4*)&Vs[s][tx*4];
        acc[0][0]+=av.x*bv.x; acc[0][1]+=av.x*bv.y; acc[0][2]+=av.x*bv.z; acc[0][3]+=av.x*bv.w;
        acc[1][0]+=av.y*bv.x; acc[1][1]+=av.y*bv.y; acc[1][2]+=av.y*bv.z; acc[1][3]+=av.y*bv.w;
        acc[2][0]+=av.z*bv.x; acc[2][1]+=av.z*bv.y; acc[2][2]+=av.z*bv.z; acc[2][3]+=av.z*bv.w;
        acc[3][0]+=av.w*bv.x; acc[3][1]+=av.w*bv.y; acc[3][2]+=av.w*bv.z; acc[3][3]+=av.w*bv.w;
    }
    size_t abase = ((size_t)bh*64 + c)*4096;
    #pragma unroll
    for (int i = 0; i < 4; i++) {
        float4 o = make_float4(acc[i][0], acc[i][1], acc[i][2], acc[i][3]);
        *(float4*)(g_chunkA + abase + (ty*4 + i)*64 + tx*4) = o;
    }
    if (t < 64) {
        float zs = 0.f;
        for (int s = 0; s < 64; s++) zs += Ks[s][t];
        g_chunkZ[((size_t)bh*64 + c)*64 + t] = zs;
    }
}

// ---------------- K3b: exclusive prefix over chunks --------------------------
__global__ void chunk_scan_kernel() {
    int bh = blockIdx.x;
    int t = threadIdx.x;
    float run[16];
    #pragma unroll
    for (int j = 0; j < 16; j++) run[j] = 0.f;
    size_t base = (size_t)bh*64*4096;
    for (int c = 0; c < 64; c++) {
        float* p = g_chunkA + base + (size_t)c*4096;
        #pragma unroll
        for (int j = 0; j < 16; j++) {
            int idx = t + 256*j;
            float tmp = p[idx];
            p[idx] = run[j];
            run[j] += tmp;
        }
    }
    if (t < 64) {
        float rz = 0.f;
        float* z = g_chunkZ + (size_t)bh*64*64;
        for (int c = 0; c < 64; c++) { float tmp = z[c*64 + t]; z[c*64 + t] = rz; rz += tmp; }
    }
}

// ---------------- K3c: chunk output ------------------------------------------
__global__ void chunk_out_kernel() {
    extern __shared__ float sm[];
    float* QdT = sm;
    float* KV  = QdT + 64*68;
    float* PT  = KV  + 64*68;
    float* Inb = PT  + 64*68;
    float* zin = Inb + 64*68;
    float* den = zin + 64;

    int c = blockIdx.x, bh = blockIdx.y;
    int t = threadIdx.x;
    int ty = t >> 4, tx = t & 15;
    if (t < 64) den[t] = 0.f;

    size_t base = ((size_t)bh*64 + c)*4096;
    #pragma unroll
    for (int r = 0; r < 4; r++) {
        int vi = t + 256*r;
        int s = vi >> 4, e0 = (vi & 15) << 2;
        float4 q = *(const float4*)(g_qf + base + s*64 + e0);
        float4 k = *(const float4*)(g_kf + base + s*64 + e0);
        QdT[(e0+0)*68 + s] = q.x; QdT[(e0+1)*68 + s] = q.y;
        QdT[(e0+2)*68 + s] = q.z; QdT[(e0+3)*68 + s] = q.w;
        KV [(e0+0)*68 + s] = k.x; KV [(e0+1)*68 + s] = k.y;
        KV [(e0+2)*68 + s] = k.z; KV [(e0+3)*68 + s] = k.w;
    }
    __syncthreads();

    {
        float acc[4][4] = {};
        #pragma unroll 8
        for (int e = 0; e < 64; e++) {
            float4 av = *(const float4*)&QdT[e*68 + ty*4];
            float4 bv = *(const float4*)&KV [e*68 + tx*4];
            acc[0][0]+=av.x*bv.x; acc[0][1]+=av.x*bv.y; acc[0][2]+=av.x*bv.z; acc[0][3]+=av.x*bv.w;
            acc[1][0]+=av.y*bv.x; acc[1][1]+=av.y*bv.y; acc[1][2]+=av.y*bv.z; acc[1][3]+=av.y*bv.w;
            acc[2][0]+=av.z*bv.x; acc[2][1]+=av.z*bv.y; acc[2][2]+=av.z*bv.z; acc[2][3]+=av.z*bv.w;
            acc[3][0]+=av.w*bv.x; acc[3][1]+=av.w*bv.y; acc[3][2]+=av.w*bv.z; acc[3][3]+=av.w*bv.w;
        }
        #pragma unroll
        for (int i = 0; i < 4; i++) {
            int tg = ty*4 + i;
            float rs = 0.f;
            #pragma unroll
            for (int j = 0; j < 4; j++) {
                int sg = tx*4 + j;
                float v = (sg <= tg) ? acc[i][j] : 0.f;
                PT[sg*68 + tg] = v;
                rs += v;
            }
            atomicAdd(&den[tg], rs);
        }
    }
    __syncthreads();

    #pragma unroll
    for (int r = 0; r < 4; r++) {
        int vi = t + 256*r;
        int s = vi >> 4, e0 = (vi & 15) << 2;
        *(float4*)&KV [s*68 + e0] = *(const float4*)(g_v + base + s*64 + e0);
        *(float4*)&Inb[s*68 + e0] = *(const float4*)(g_chunkA + base + s*64 + e0);
    }
    if (t < 64) zin[t] = g_chunkZ[((size_t)bh*64 + c)*64 + t];
    __syncthreads();

    if (t < 64) {
        float s = 0.f;
        for (int e = 0; e < 64; e++) s += QdT[e*68 + t]*zin[e];
        den[t] += s;
    }
    __syncthreads();

    float acc[4][4] = {};
    #pragma unroll 8
    for (int s = 0; s < 64; s++) {
        float4 wv = *(const float4*)&PT[s*68 + ty*4];
        float4 xv = *(const float4*)&KV[s*68 + tx*4];
        acc[0][0]+=wv.x*xv.x; acc[0][1]+=wv.x*xv.y; acc[0][2]+=wv.x*xv.z; acc[0][3]+=wv.x*xv.w;
        acc[1][0]+=wv.y*xv.x; acc[1][1]+=wv.y*xv.y; acc[1][2]+=wv.y*xv.z; acc[1][3]+=wv.y*xv.w;
        acc[2][0]+=wv.z*xv.x; acc[2][1]+=wv.z*xv.y; acc[2][2]+=wv.z*xv.z; acc[2][3]+=wv.z*xv.w;
        acc[3][0]+=wv.w*xv.x; acc[3][1]+=wv.w*xv.y; acc[3][2]+=wv.w*xv.z; acc[3][3]+=wv.w*xv.w;
    }
    #pragma unroll 8
    for (int e = 0; e < 64; e++) {
        float4 wv = *(const float4*)&QdT[e*68 + ty*4];
        float4 xv = *(const float4*)&Inb[e*68 + tx*4];
        acc[0][0]+=wv.x*xv.x; acc[0][1]+=wv.x*xv.y; acc[0][2]+=wv.x*xv.z; acc[0][3]+=wv.x*xv.w;
        acc[1][0]+=wv.y*xv.x; acc[1][1]+=wv.y*xv.y; acc[1][2]+=wv.y*xv.z; acc[1][3]+=wv.y*xv.w;
        acc[2][0]+=wv.z*xv.x; acc[2][1]+=wv.z*xv.y; acc[2][2]+=wv.z*xv.z; acc[2][3]+=wv.z*xv.w;
        acc[3][0]+=wv.w*xv.x; acc[3][1]+=wv.w*xv.y; acc[3][2]+=wv.w*xv.z; acc[3][3]+=wv.w*xv.w;
    }
    int b = bh >> 3, h = bh & 7;
    #pragma unroll
    for (int i = 0; i < 4; i++) {
        int tg = ty*4 + i;
        float inv = 1.f/(den[tg] + 1e-6f);
        int l = c*64 + tg;
        float4 o = make_float4(acc[i][0]*inv, acc[i][1]*inv, acc[i][2]*inv, acc[i][3]*inv);
        *(float4*)(g_att + ((size_t)b*4096 + l)*512 + h*64 + tx*4) = o;
    }
}

// ---------------- K5: in-place RMSNorm ---------------------------------------
__global__ void rmsnorm_kernel(float* __restrict__ out,
                               const float* __restrict__ scale) {
    int m = blockIdx.x;
    int t = threadIdx.x;
    float4 v = *(float4*)(out + (size_t)m*512 + t*4);
    float ss = v.x*v.x + v.y*v.y + v.z*v.z + v.w*v.w;
    #pragma unroll
    for (int o = 16; o > 0; o >>= 1) ss += __shfl_xor_sync(0xffffffffu, ss, o);
    __shared__ float red[4];
    if ((t & 31) == 0) red[t >> 5] = ss;
    __syncthreads();
    float tot = red[0] + red[1] + red[2] + red[3];
    float inv = rsqrtf(tot * (1.f/512.f) + 1e-8f);
    float4 sc = *(const float4*)(scale + t*4);
    v.x *= inv*sc.x; v.y *= inv*sc.y; v.z *= inv*sc.z; v.w *= inv*sc.w;
    *(float4*)(out + (size_t)m*512 + t*4) = v;
}

// ---------------- launch ------------------------------------------------------
extern "C" void kernel_launch(void* const* d_in, const int* in_sizes, int n_in,
                              void* d_out, int out_size) {
    const float* x          = (const float*)d_in[0];
    const float* qkv_w      = (const float*)d_in[1];
    const float* qkv_b      = (const float*)d_in[2];
    const float* out_w      = (const float*)d_in[3];
    const float* out_b      = (const float*)d_in[4];
    const float* decay_w    = (const float*)d_in[5];
    const float* decay_b    = (const float*)d_in[6];
    const float* norm_scale = (const float*)d_in[7];
    float* out = (float*)d_out;

    qkv_gemm_kernel<<<dim3(12, 64), 256>>>(x, qkv_w, qkv_b);
    decay_kernel<<<1024, 256>>>(x, decay_w, decay_b);
    cumsum_kernel<<<16, 128>>>();
    apply_decay_kernel<<<4096, 256>>>();
    chunk_sum_kernel<<<dim3(64, 16), 256>>>();
    chunk_scan_kernel<<<16, 256>>>();

    const int dyn = (4*64*68 + 128) * sizeof(float);
    cudaFuncSetAttribute(chunk_out_kernel,
                         cudaFuncAttributeMaxDynamicSharedMemorySize, dyn);
    chunk_out_kernel<<<dim3(64, 16), 256, dyn>>>();

    out_gemm_kernel<<<dim3(4, 64), 256>>>(out_w, out_b, out);
    rmsnorm_kernel<<<8192, 128>>>(out, norm_scale);
}